// round 1
// baseline (speedup 1.0000x reference)
#include <cuda_runtime.h>
#include <math.h>

#define EMBED 256
#define NH 8
#define NL 3
#define NP 4
#define HD 32
#define P2 8
#define B_ 4
#define NQ 300
#define NK 17
#define LQ (NQ * NK)        // 5100
#define LTOT 13125          // 100*100 + 50*50 + 25*25
#define MQ (B_ * LQ)        // 20400 query rows
#define MV (B_ * LTOT)      // 52500 value rows

__constant__ int c_lvlH[NL] = {100, 50, 25};
__constant__ int c_lvlW[NL] = {100, 50, 25};
__constant__ int c_lvlS[NL] = {0, 10000, 12500};

// scratch (static device allocations are allowed)
__device__ float g_v[B_ * NH * LTOT * HD];     // [b][h][pix][d]  53.76 MB
__device__ float g_off[MQ * (NH * NL * NP * 4)]; // [bq][384]
__device__ float g_aw[MQ * (NH * NL * NP)];      // [bq][96]
__device__ float g_tmp[MQ * EMBED];              // [bq][h*32+d]

// ---------------------------------------------------------------------------
// Tiled fp32 GEMM: C[M,N] = A[M,K] @ B[N,K]^T + bias[N]
// MODE 0: C row-major [M,N].  MODE 1: scatter to g_v layout [b][h][l][d].
// BM=BN=64, BK=16, 256 threads, 4x4 per thread, float4 global loads.
// ---------------------------------------------------------------------------
template <int MODE>
__global__ void gemm_tn(const float* __restrict__ A, const float* __restrict__ Bm,
                        const float* __restrict__ bias, float* __restrict__ C,
                        int M, int N, int K) {
    const int BM = 64, BN = 64, BK = 16;
    __shared__ float As[BK][BM + 4];
    __shared__ float Bs[BK][BN + 4];

    int tid = threadIdx.x;
    int tx = tid % 16, ty = tid / 16;
    int bm = blockIdx.y * BM, bn = blockIdx.x * BN;

    int lrow = tid / 4;            // 0..63
    int lk   = (tid % 4) * 4;      // 0,4,8,12

    float acc[4][4];
#pragma unroll
    for (int i = 0; i < 4; i++)
#pragma unroll
        for (int j = 0; j < 4; j++) acc[i][j] = 0.f;

    for (int k0 = 0; k0 < K; k0 += BK) {
        // load A tile
        {
            int gr = bm + lrow;
            float4 v = make_float4(0.f, 0.f, 0.f, 0.f);
            if (gr < M)
                v = *reinterpret_cast<const float4*>(&A[(size_t)gr * K + k0 + lk]);
            As[lk + 0][lrow] = v.x; As[lk + 1][lrow] = v.y;
            As[lk + 2][lrow] = v.z; As[lk + 3][lrow] = v.w;
        }
        // load B tile
        {
            int gc = bn + lrow;
            float4 v = make_float4(0.f, 0.f, 0.f, 0.f);
            if (gc < N)
                v = *reinterpret_cast<const float4*>(&Bm[(size_t)gc * K + k0 + lk]);
            Bs[lk + 0][lrow] = v.x; Bs[lk + 1][lrow] = v.y;
            Bs[lk + 2][lrow] = v.z; Bs[lk + 3][lrow] = v.w;
        }
        __syncthreads();
#pragma unroll
        for (int k = 0; k < BK; k++) {
            float a[4], bb[4];
#pragma unroll
            for (int i = 0; i < 4; i++) a[i] = As[k][ty * 4 + i];
#pragma unroll
            for (int j = 0; j < 4; j++) bb[j] = Bs[k][tx * 4 + j];
#pragma unroll
            for (int i = 0; i < 4; i++)
#pragma unroll
                for (int j = 0; j < 4; j++) acc[i][j] += a[i] * bb[j];
        }
        __syncthreads();
    }

#pragma unroll
    for (int i = 0; i < 4; i++) {
        int row = bm + ty * 4 + i;
        if (row >= M) continue;
#pragma unroll
        for (int j = 0; j < 4; j++) {
            int col = bn + tx * 4 + j;
            if (col >= N) continue;
            float val = acc[i][j] + bias[col];
            if (MODE == 0) {
                C[(size_t)row * N + col] = val;
            } else {
                // value projection scatter: row = b*LTOT + l ; col = h*HD + d
                int b = row / LTOT, l = row % LTOT;
                int h = col / HD,  d = col % HD;
                C[(((size_t)(b * NH + h)) * LTOT + l) * HD + d] = val;
            }
        }
    }
}

// softmax over groups of 12 (NL*NP), layout [bq][h][12] contiguous
__global__ void softmax12(float* __restrict__ aw, int total) {
    int g = blockIdx.x * blockDim.x + threadIdx.x;
    if (g >= total) return;
    float* p = aw + (size_t)g * 12;
    float m = -1e30f;
#pragma unroll
    for (int i = 0; i < 12; i++) m = fmaxf(m, p[i]);
    float e[12], s = 0.f;
#pragma unroll
    for (int i = 0; i < 12; i++) { e[i] = __expf(p[i] - m); s += e[i]; }
    float inv = 1.f / s;
#pragma unroll
    for (int i = 0; i < 12; i++) p[i] = e[i] * inv;
}

// ---------------------------------------------------------------------------
// Bilinear sampling + attention-weighted accumulation.
// One block per (b,q); one warp per head; lane = channel d.
// ---------------------------------------------------------------------------
__global__ void __launch_bounds__(NH * 32)
sample_kernel(const float* __restrict__ ref_l, const float* __restrict__ ref_r,
              const float* __restrict__ off, const float* __restrict__ aw,
              float* __restrict__ out) {
    int bq = blockIdx.x;                 // 0..MQ-1
    int b = bq / LQ, q = bq % LQ;
    int h = threadIdx.x >> 5;
    int d = threadIdx.x & 31;
    int nqi = q / NK, nki = q % NK;

    const float* offp = off + (size_t)bq * (NH * NL * NP * 4) + h * (NL * NP * 4);
    const float* awp  = aw  + (size_t)bq * (NH * NL * NP) + h * (NL * NP);
    const float* vb   = g_v + ((size_t)(b * NH + h)) * LTOT * HD + d;

    float acc = 0.f;
#pragma unroll
    for (int l = 0; l < NL; l++) {
        int H = c_lvlH[l], W = c_lvlW[l];
        const float* vlev = vb + (size_t)c_lvlS[l] * HD;
        float fW = (float)W, fH = (float)H;
        // refs: [b][nq][nl][nk][2]
        size_t rbase = ((((size_t)b * NQ + nqi) * NL + l) * NK + nki) * 2;
        float rlx = __ldg(&ref_l[rbase]);
        float rly = __ldg(&ref_l[rbase + 1]);
        float rrx = __ldg(&ref_r[rbase]);
        float rry = __ldg(&ref_r[rbase + 1]);
#pragma unroll
        for (int p = 0; p < P2; p++) {
            int pp = p & 3;
            int sbase = (l * NP + pp) * 4 + ((p < NP) ? 0 : 2);
            float ox = __ldg(&offp[sbase]);
            float oy = __ldg(&offp[sbase + 1]);
            float w  = __ldg(&awp[l * NP + pp]);
            float lx = ((p < NP) ? rlx : rrx) + ox / fW;
            float ly = ((p < NP) ? rly : rry) + oy / fH;
            float x = lx * fW - 0.5f;
            float y = ly * fH - 0.5f;
            float x0f = floorf(x), y0f = floorf(y);
            int x0 = (int)x0f, y0 = (int)y0f;
            float tx = x - x0f, ty = y - y0f;
            float sval = 0.f;
#pragma unroll
            for (int dy = 0; dy < 2; dy++) {
#pragma unroll
                for (int dx = 0; dx < 2; dx++) {
                    int xi = x0 + dx, yi = y0 + dy;
                    if (xi >= 0 && xi < W && yi >= 0 && yi < H) {
                        float wt = (dx ? tx : 1.f - tx) * (dy ? ty : 1.f - ty);
                        sval += wt * __ldg(&vlev[((size_t)yi * W + xi) * HD]);
                    }
                }
            }
            acc += w * sval;
        }
    }
    out[(size_t)bq * EMBED + h * HD + d] = acc;
}

extern "C" void kernel_launch(void* const* d_in, const int* in_sizes, int n_in,
                              void* d_out, int out_size) {
    const float* query = (const float*)d_in[0];
    const float* ref_l = (const float*)d_in[1];
    const float* ref_r = (const float*)d_in[2];
    const float* value = (const float*)d_in[3];
    // d_in[4]: spatial shapes (static, hardcoded); d_in[5]: value_mask (all false)
    const float* W_off  = (const float*)d_in[6];
    const float* b_off  = (const float*)d_in[7];
    const float* W_attn = (const float*)d_in[8];
    const float* b_attn = (const float*)d_in[9];
    const float* W_val  = (const float*)d_in[10];
    const float* b_val  = (const float*)d_in[11];
    const float* W_out  = (const float*)d_in[12];
    const float* b_out  = (const float*)d_in[13];
    float* out = (float*)d_out;

    float *gv, *goff, *gaw, *gtmp;
    cudaGetSymbolAddress((void**)&gv, g_v);
    cudaGetSymbolAddress((void**)&goff, g_off);
    cudaGetSymbolAddress((void**)&gaw, g_aw);
    cudaGetSymbolAddress((void**)&gtmp, g_tmp);

    // 1. value projection: [MV,512] @ W_val[256,512]^T -> g_v (scattered layout)
    {
        dim3 grid((EMBED + 63) / 64, (MV + 63) / 64);
        gemm_tn<1><<<grid, 256>>>(value, W_val, b_val, gv, MV, EMBED, EMBED * 2);
    }
    // 2. offsets: [MQ,256] @ W_off[384,256]^T
    {
        dim3 grid((NH * NL * NP * 4 + 63) / 64, (MQ + 63) / 64);
        gemm_tn<0><<<grid, 256>>>(query, W_off, b_off, goff, MQ, NH * NL * NP * 4, EMBED);
    }
    // 3. attention logits: [MQ,256] @ W_attn[96,256]^T
    {
        dim3 grid((NH * NL * NP + 63) / 64, (MQ + 63) / 64);
        gemm_tn<0><<<grid, 256>>>(query, W_attn, b_attn, gaw, MQ, NH * NL * NP, EMBED);
    }
    // 3b. softmax over NL*NP=12 per (bq,h)
    {
        int total = MQ * NH;
        softmax12<<<(total + 255) / 256, 256>>>(gaw, total);
    }
    // 4. deformable sampling
    sample_kernel<<<MQ, NH * 32>>>(ref_l, ref_r, goff, gaw, gtmp);
    // 5. output projection: [MQ,256] @ W_out[256,256]^T -> d_out
    {
        dim3 grid((EMBED + 63) / 64, (MQ + 63) / 64);
        gemm_tn<0><<<grid, 256>>>(gtmp, W_out, b_out, out, MQ, EMBED, EMBED);
    }
}

// round 2
// speedup vs baseline: 1.2737x; 1.2737x over previous
#include <cuda_runtime.h>
#include <mma.h>
#include <math.h>

using namespace nvcuda;

#define EMBED 256
#define NH 8
#define NL 3
#define NP 4
#define HD 32
#define P2 8
#define B_ 4
#define NQ 300
#define NK 17
#define LQ (NQ * NK)        // 5100
#define LTOT 13125          // 100*100 + 50*50 + 25*25
#define MQ (B_ * LQ)        // 20400 query rows
#define MV (B_ * LTOT)      // 52500 value rows

__constant__ int c_lvlH[NL] = {100, 50, 25};
__constant__ int c_lvlW[NL] = {100, 50, 25};
__constant__ int c_lvlS[NL] = {0, 10000, 12500};

// scratch (static device allocations are allowed)
__device__ float g_v[B_ * NH * LTOT * HD];       // [b][h][pix][d]  53.76 MB
__device__ float g_off[MQ * (NH * NL * NP * 4)]; // [bq][384]
__device__ float g_aw[MQ * (NH * NL * NP)];      // [bq][96]
__device__ float g_tmp[MQ * EMBED];              // [bq][h*32+d]

// ---------------------------------------------------------------------------
// tf32 WMMA GEMM: C[M,N] = A[M,K] @ B[N,K]^T + bias[N]
// BM=128, BN=64, BK=32. 8 warps (4x2), each warp 32x32 via 2x2 m16n16k8 frags.
// MODE 0: row-major out. MODE 1: scatter to g_v layout [b][h][pix][d].
// ---------------------------------------------------------------------------
#define BM 128
#define BN 64
#define BK 32
#define LDA 36   // BK + 4 (36*4B = 144B row stride, 16B aligned)
#define LDC 68   // BN + 4

template <int MODE>
__global__ void __launch_bounds__(256)
gemm_wmma(const float* __restrict__ A, const float* __restrict__ Bm,
          const float* __restrict__ bias, float* __restrict__ C,
          int M, int N, int K) {
    // union: k-loop uses As(128x36) + Bs(64x36) = 6912 floats;
    // epilogue uses Cs(128x68) = 8704 floats.
    __shared__ float smem[BM * LDC];
    float (*As)[LDA] = (float(*)[LDA])smem;
    float (*Bs)[LDA] = (float(*)[LDA])(smem + BM * LDA);
    float (*Cs)[LDC] = (float(*)[LDC])smem;

    int tid = threadIdx.x;
    int warp = tid >> 5;
    int wr = warp >> 1;          // 0..3 (rows of 32)
    int wc = warp & 1;           // 0..1 (cols of 32)
    int bm = blockIdx.y * BM, bn = blockIdx.x * BN;

    wmma::fragment<wmma::accumulator, 16, 16, 8, float> acc[2][2];
#pragma unroll
    for (int i = 0; i < 2; i++)
#pragma unroll
        for (int j = 0; j < 2; j++) wmma::fill_fragment(acc[i][j], 0.f);

    int r  = tid >> 3;           // 0..31
    int kk = (tid & 7) * 4;      // 0..28

    for (int k0 = 0; k0 < K; k0 += BK) {
        // A tile: 128x32, four float4 per thread
#pragma unroll
        for (int it = 0; it < 4; it++) {
            int row = r + it * 32;
            int gr = bm + row;
            float4 v = make_float4(0.f, 0.f, 0.f, 0.f);
            if (gr < M) v = *reinterpret_cast<const float4*>(&A[(size_t)gr * K + k0 + kk]);
            *reinterpret_cast<float4*>(&As[row][kk]) = v;
        }
        // B tile: 64x32, two float4 per thread  (Bs[n][k])
#pragma unroll
        for (int it = 0; it < 2; it++) {
            int row = r + it * 32;
            int gc = bn + row;
            float4 v = make_float4(0.f, 0.f, 0.f, 0.f);
            if (gc < N) v = *reinterpret_cast<const float4*>(&Bm[(size_t)gc * K + k0 + kk]);
            *reinterpret_cast<float4*>(&Bs[row][kk]) = v;
        }
        __syncthreads();
#pragma unroll
        for (int ks = 0; ks < BK; ks += 8) {
            wmma::fragment<wmma::matrix_a, 16, 16, 8, wmma::precision::tf32, wmma::row_major> af[2];
            wmma::fragment<wmma::matrix_b, 16, 16, 8, wmma::precision::tf32, wmma::col_major> bf[2];
#pragma unroll
            for (int i = 0; i < 2; i++) {
                wmma::load_matrix_sync(af[i], &As[wr * 32 + i * 16][ks], LDA);
#pragma unroll
                for (int t = 0; t < af[i].num_elements; t++)
                    af[i].x[t] = wmma::__float_to_tf32(af[i].x[t]);
            }
#pragma unroll
            for (int j = 0; j < 2; j++) {
                wmma::load_matrix_sync(bf[j], &Bs[wc * 32 + j * 16][ks], LDA);
#pragma unroll
                for (int t = 0; t < bf[j].num_elements; t++)
                    bf[j].x[t] = wmma::__float_to_tf32(bf[j].x[t]);
            }
#pragma unroll
            for (int i = 0; i < 2; i++)
#pragma unroll
                for (int j = 0; j < 2; j++)
                    wmma::mma_sync(acc[i][j], af[i], bf[j], acc[i][j]);
        }
        __syncthreads();
    }

    // epilogue: park accumulators in smem, then bias + (scatter) store
#pragma unroll
    for (int i = 0; i < 2; i++)
#pragma unroll
        for (int j = 0; j < 2; j++)
            wmma::store_matrix_sync(&Cs[wr * 32 + i * 16][wc * 32 + j * 16],
                                    acc[i][j], LDC, wmma::mem_row_major);
    __syncthreads();

    for (int i = tid; i < BM * BN; i += 256) {
        int row = i >> 6;       // /BN
        int col = i & (BN - 1);
        int gr = bm + row, gc = bn + col;
        if (gr < M && gc < N) {
            float val = Cs[row][col] + bias[gc];
            if (MODE == 0) {
                C[(size_t)gr * N + gc] = val;
            } else {
                int b = gr / LTOT, l = gr % LTOT;
                int h = gc >> 5, d = gc & 31;
                C[(((size_t)(b * NH + h)) * LTOT + l) * HD + d] = val;
            }
        }
    }
}

// softmax over groups of 12 (NL*NP), layout [bq][h][12] contiguous
__global__ void softmax12(float* __restrict__ aw, int total) {
    int g = blockIdx.x * blockDim.x + threadIdx.x;
    if (g >= total) return;
    float* p = aw + (size_t)g * 12;
    float m = -1e30f;
#pragma unroll
    for (int i = 0; i < 12; i++) m = fmaxf(m, p[i]);
    float e[12], s = 0.f;
#pragma unroll
    for (int i = 0; i < 12; i++) { e[i] = __expf(p[i] - m); s += e[i]; }
    float inv = 1.f / s;
#pragma unroll
    for (int i = 0; i < 12; i++) p[i] = e[i] * inv;
}

// ---------------------------------------------------------------------------
// Bilinear sampling + attention-weighted accumulation.
// One block per (b,q); one warp per head; lane = channel d.
// ---------------------------------------------------------------------------
__global__ void __launch_bounds__(NH * 32)
sample_kernel(const float* __restrict__ ref_l, const float* __restrict__ ref_r,
              const float* __restrict__ off, const float* __restrict__ aw,
              float* __restrict__ out) {
    int bq = blockIdx.x;                 // 0..MQ-1
    int b = bq / LQ, q = bq % LQ;
    int h = threadIdx.x >> 5;
    int d = threadIdx.x & 31;
    int nqi = q / NK, nki = q % NK;

    const float* offp = off + (size_t)bq * (NH * NL * NP * 4) + h * (NL * NP * 4);
    const float* awp  = aw  + (size_t)bq * (NH * NL * NP) + h * (NL * NP);
    const float* vb   = g_v + ((size_t)(b * NH + h)) * LTOT * HD + d;

    float acc = 0.f;
#pragma unroll
    for (int l = 0; l < NL; l++) {
        int H = c_lvlH[l], W = c_lvlW[l];
        const float* vlev = vb + (size_t)c_lvlS[l] * HD;
        float fW = (float)W, fH = (float)H;
        // refs: [b][nq][nl][nk][2]
        size_t rbase = ((((size_t)b * NQ + nqi) * NL + l) * NK + nki) * 2;
        float rlx = __ldg(&ref_l[rbase]);
        float rly = __ldg(&ref_l[rbase + 1]);
        float rrx = __ldg(&ref_r[rbase]);
        float rry = __ldg(&ref_r[rbase + 1]);
#pragma unroll
        for (int p = 0; p < P2; p++) {
            int pp = p & 3;
            int sbase = (l * NP + pp) * 4 + ((p < NP) ? 0 : 2);
            float ox = __ldg(&offp[sbase]);
            float oy = __ldg(&offp[sbase + 1]);
            float w  = __ldg(&awp[l * NP + pp]);
            float lx = ((p < NP) ? rlx : rrx) + ox / fW;
            float ly = ((p < NP) ? rly : rry) + oy / fH;
            float x = lx * fW - 0.5f;
            float y = ly * fH - 0.5f;
            float x0f = floorf(x), y0f = floorf(y);
            int x0 = (int)x0f, y0 = (int)y0f;
            float tx = x - x0f, ty = y - y0f;
            float sval = 0.f;
#pragma unroll
            for (int dy = 0; dy < 2; dy++) {
#pragma unroll
                for (int dx = 0; dx < 2; dx++) {
                    int xi = x0 + dx, yi = y0 + dy;
                    if (xi >= 0 && xi < W && yi >= 0 && yi < H) {
                        float wt = (dx ? tx : 1.f - tx) * (dy ? ty : 1.f - ty);
                        sval += wt * __ldg(&vlev[((size_t)yi * W + xi) * HD]);
                    }
                }
            }
            acc += w * sval;
        }
    }
    out[(size_t)bq * EMBED + h * HD + d] = acc;
}

extern "C" void kernel_launch(void* const* d_in, const int* in_sizes, int n_in,
                              void* d_out, int out_size) {
    const float* query = (const float*)d_in[0];
    const float* ref_l = (const float*)d_in[1];
    const float* ref_r = (const float*)d_in[2];
    const float* value = (const float*)d_in[3];
    // d_in[4]: spatial shapes (static, hardcoded); d_in[5]: value_mask (all false)
    const float* W_off  = (const float*)d_in[6];
    const float* b_off  = (const float*)d_in[7];
    const float* W_attn = (const float*)d_in[8];
    const float* b_attn = (const float*)d_in[9];
    const float* W_val  = (const float*)d_in[10];
    const float* b_val  = (const float*)d_in[11];
    const float* W_out  = (const float*)d_in[12];
    const float* b_out  = (const float*)d_in[13];
    float* out = (float*)d_out;

    float *gv, *goff, *gaw, *gtmp;
    cudaGetSymbolAddress((void**)&gv, g_v);
    cudaGetSymbolAddress((void**)&goff, g_off);
    cudaGetSymbolAddress((void**)&gaw, g_aw);
    cudaGetSymbolAddress((void**)&gtmp, g_tmp);

    // 1. value projection: [MV,512] @ W_val[256,512]^T -> g_v (scattered layout)
    {
        dim3 grid((EMBED + BN - 1) / BN, (MV + BM - 1) / BM);
        gemm_wmma<1><<<grid, 256>>>(value, W_val, b_val, gv, MV, EMBED, EMBED * 2);
    }
    // 2. offsets: [MQ,256] @ W_off[384,256]^T
    {
        dim3 grid((NH * NL * NP * 4 + BN - 1) / BN, (MQ + BM - 1) / BM);
        gemm_wmma<0><<<grid, 256>>>(query, W_off, b_off, goff, MQ, NH * NL * NP * 4, EMBED);
    }
    // 3. attention logits: [MQ,256] @ W_attn[96,256]^T
    {
        dim3 grid((NH * NL * NP + BN - 1) / BN, (MQ + BM - 1) / BM);
        gemm_wmma<0><<<grid, 256>>>(query, W_attn, b_attn, gaw, MQ, NH * NL * NP, EMBED);
    }
    // 3b. softmax over NL*NP=12 per (bq,h)
    {
        int total = MQ * NH;
        softmax12<<<(total + 255) / 256, 256>>>(gaw, total);
    }
    // 4. deformable sampling
    sample_kernel<<<MQ, NH * 32>>>(ref_l, ref_r, goff, gaw, gtmp);
    // 5. output projection: [MQ,256] @ W_out[256,256]^T -> d_out
    {
        dim3 grid((EMBED + BN - 1) / BN, (MQ + BM - 1) / BM);
        gemm_wmma<0><<<grid, 256>>>(gtmp, W_out, b_out, out, MQ, EMBED, EMBED);
    }
}